// round 9
// baseline (speedup 1.0000x reference)
#include <cuda_runtime.h>
#include <cuda_bf16.h>
#include <cuda_fp16.h>

#define N_NODES 50000
#define N_EDGES 800000
#define D 64
#define NBLK ((N_NODES + 255) / 256)   // 196

// ---------------------------------------------------------------------------
// Static device scratch. g_cnt zero at load; scatter_idx re-zeroes it each
// run (after scanfin has consumed it) -> graph-replay deterministic.
// ---------------------------------------------------------------------------
__device__ int    g_cnt[N_NODES];
__device__ int    g_offs[N_NODES + 1];
__device__ int    g_cursor[N_NODES];
__device__ int    g_sorted[N_EDGES];
__device__ float  g_Y[N_NODES * D];            // Y = feat @ W^T (fp32)
__device__ __half g_Yh[N_NODES * D];           // fp16 copy for gather traffic

// Side stream + events for graph-forked overlap (created at program init).
static cudaStream_t g_side;
static cudaEvent_t  g_evFork, g_evJoin;
namespace {
struct _Init {
    _Init() {
        cudaStreamCreateWithFlags(&g_side, cudaStreamNonBlocking);
        cudaEventCreateWithFlags(&g_evFork, cudaEventDisableTiming);
        cudaEventCreateWithFlags(&g_evJoin, cudaEventDisableTiming);
    }
} _g_init;
}

// ---------------------------------------------------------------------------
// 1) Histogram, 4 edges/thread (int4 loads, 4 independent REDs overlap)
// ---------------------------------------------------------------------------
__global__ __launch_bounds__(256) void hist_kernel(const int4* __restrict__ dst4,
                                                   int* __restrict__ cnt)
{
    int q = blockIdx.x * blockDim.x + threadIdx.x;
    if (q >= N_EDGES / 4) return;
    int4 d = __ldg(dst4 + q);
    atomicAdd(&cnt[d.x], 1);
    atomicAdd(&cnt[d.y], 1);
    atomicAdd(&cnt[d.z], 1);
    atomicAdd(&cnt[d.w], 1);
}

// ---------------------------------------------------------------------------
// 2) Merged scan: each block sums cnt[0..bid*256) directly for its base
//    (L2-hot, int4-vectorized), then scans its own 256 counters.
//    Does NOT zero cnt (other blocks still read it) — scatter_idx does.
// ---------------------------------------------------------------------------
__global__ __launch_bounds__(256) void scanfin_kernel(
    const int* __restrict__ cnt, int* __restrict__ offs,
    int* __restrict__ cursor)
{
    __shared__ int sm[256];
    __shared__ int sbase[8];
    const int t = threadIdx.x;
    const int bid = blockIdx.x;

    // Base = sum of cnt[0 .. bid*256): bid*64 int4 elements, coalesced
    const int4* cnt4 = (const int4*)cnt;
    int nq = bid * 64;
    int bv = 0;
    for (int i = t; i < nq; i += 256) {
        int4 v = __ldg(cnt4 + i);
        bv += (v.x + v.y) + (v.z + v.w);
    }
#pragma unroll
    for (int o = 16; o > 0; o >>= 1) bv += __shfl_down_sync(~0u, bv, o);
    if ((t & 31) == 0) sbase[t >> 5] = bv;

    // Local counters
    int idx = bid * 256 + t;
    int c = (idx < N_NODES) ? __ldg(cnt + idx) : 0;
    sm[t] = c;
    __syncthreads();

    int base = sbase[0] + sbase[1] + sbase[2] + sbase[3] +
               sbase[4] + sbase[5] + sbase[6] + sbase[7];

    for (int off = 1; off < 256; off <<= 1) {
        int u = (t >= off) ? sm[t - off] : 0;
        __syncthreads();
        sm[t] += u;
        __syncthreads();
    }
    int off = base + sm[t] - c;   // exclusive prefix
    if (idx < N_NODES) {
        offs[idx]   = off;
        cursor[idx] = off;
        if (idx == N_NODES - 1) offs[N_NODES] = off + c;  // = N_EDGES
    }
}

// ---------------------------------------------------------------------------
// 3) Scatter, 4 edges/thread (4 independent ATOM chains overlap their
//    318-cyc latencies). Also re-zeroes cnt for the next graph replay.
// ---------------------------------------------------------------------------
__global__ __launch_bounds__(256) void scatter_idx_kernel(
    const int4* __restrict__ src4, const int4* __restrict__ dst4,
    int* __restrict__ cursor, int* __restrict__ sorted,
    int* __restrict__ cnt)
{
    int q = blockIdx.x * blockDim.x + threadIdx.x;
    if (q < N_NODES) cnt[q] = 0;              // replay reset (reads done)
    if (q >= N_EDGES / 4) return;
    int4 s = __ldg(src4 + q);
    int4 d = __ldg(dst4 + q);
    int p0 = atomicAdd(&cursor[d.x], 1);
    int p1 = atomicAdd(&cursor[d.y], 1);
    int p2 = atomicAdd(&cursor[d.z], 1);
    int p3 = atomicAdd(&cursor[d.w], 1);
    sorted[p0] = s.x;
    sorted[p1] = s.y;
    sorted[p2] = s.z;
    sorted[p3] = s.w;
}

// ---------------------------------------------------------------------------
// 4) Y = feat @ W^T  (proven scalar-FFMA body) + fp16 copy for the gather
// ---------------------------------------------------------------------------
#define GROWS 96

__global__ __launch_bounds__(GROWS) void gemm_y_kernel(
    const float4* __restrict__ feat, const float4* __restrict__ W,
    float4* __restrict__ Y, uint2* __restrict__ Yh)
{
    __shared__ float4 Wsm[64 * 16];       // Wsm[j*16 + kq] = W[j][4kq..4kq+3]
    __shared__ float4 tile[GROWS * 17];   // padded row stride

    const int tid  = threadIdx.x;
    const int row0 = blockIdx.x * GROWS;

    for (int i = tid; i < 64 * 16; i += GROWS) Wsm[i] = W[i];

    for (int i = tid; i < GROWS * 16; i += GROWS) {
        int r = i >> 4, c = i & 15;
        int gr = row0 + r;
        float4 v = make_float4(0.f, 0.f, 0.f, 0.f);
        if (gr < N_NODES) v = feat[gr * 16 + c];
        tile[r * 17 + c] = v;
    }
    __syncthreads();

    float acc[64];
#pragma unroll
    for (int j = 0; j < 64; j++) acc[j] = 0.f;

    for (int kq = 0; kq < 16; kq++) {           // NOT unrolled (I$)
        float4 v = tile[tid * 17 + kq];
#pragma unroll
        for (int j = 0; j < 64; j++) {          // broadcast LDS.128 of W
            float4 w = Wsm[j * 16 + kq];
            acc[j] += v.x * w.x + v.y * w.y + v.z * w.z + v.w * w.w;
        }
    }

    __syncthreads();
#pragma unroll
    for (int q = 0; q < 16; q++)
        tile[tid * 17 + q] =
            make_float4(acc[4 * q], acc[4 * q + 1], acc[4 * q + 2], acc[4 * q + 3]);
    __syncthreads();

    for (int i = tid; i < GROWS * 16; i += GROWS) {
        int r = i >> 4, c = i & 15;
        int gr = row0 + r;
        if (gr < N_NODES) {
            float4 v = tile[r * 17 + c];
            Y[gr * 16 + c] = v;
            __half2 h0 = __floats2half2_rn(v.x, v.y);
            __half2 h1 = __floats2half2_rn(v.z, v.w);
            uint2 hp;
            hp.x = *(unsigned int*)&h0;
            hp.y = *(unsigned int*)&h1;
            Yh[gr * 16 + c] = hp;
        }
    }
}

// ---------------------------------------------------------------------------
// 5) Final gather: out[g] = (1+eps)*Y[g] + sum_e Yh[src_e] + b
//    (proven: fp16 neighbor reads, fp32 accumulation + residual)
// ---------------------------------------------------------------------------
__global__ __launch_bounds__(256) void gather_final_kernel(
    const float4* __restrict__ Y, const uint2* __restrict__ Yh,
    const int* __restrict__ offs, const int* __restrict__ sorted,
    const float* __restrict__ eps, const float4* __restrict__ b4,
    float4* __restrict__ out)
{
    int g = (blockIdx.x * blockDim.x + threadIdx.x) >> 4;   // node
    int c = threadIdx.x & 15;
    if (g >= N_NODES) return;

    int beg = __ldg(offs + g);
    int end = __ldg(offs + g + 1);

    float4 a = make_float4(0.f, 0.f, 0.f, 0.f);
    int e = beg;
    for (; e + 4 <= end; e += 4) {
        int s0 = __ldg(sorted + e);
        int s1 = __ldg(sorted + e + 1);
        int s2 = __ldg(sorted + e + 2);
        int s3 = __ldg(sorted + e + 3);
        uint2 p0 = Yh[s0 * 16 + c];
        uint2 p1 = Yh[s1 * 16 + c];
        uint2 p2 = Yh[s2 * 16 + c];
        uint2 p3 = Yh[s3 * 16 + c];
        float2 f;
        f = __half22float2(*(__half2*)&p0.x); a.x += f.x; a.y += f.y;
        f = __half22float2(*(__half2*)&p0.y); a.z += f.x; a.w += f.y;
        f = __half22float2(*(__half2*)&p1.x); a.x += f.x; a.y += f.y;
        f = __half22float2(*(__half2*)&p1.y); a.z += f.x; a.w += f.y;
        f = __half22float2(*(__half2*)&p2.x); a.x += f.x; a.y += f.y;
        f = __half22float2(*(__half2*)&p2.y); a.z += f.x; a.w += f.y;
        f = __half22float2(*(__half2*)&p3.x); a.x += f.x; a.y += f.y;
        f = __half22float2(*(__half2*)&p3.y); a.z += f.x; a.w += f.y;
    }
    for (; e < end; e++) {
        int s = __ldg(sorted + e);
        uint2 p = Yh[s * 16 + c];
        float2 f;
        f = __half22float2(*(__half2*)&p.x); a.x += f.x; a.y += f.y;
        f = __half22float2(*(__half2*)&p.y); a.z += f.x; a.w += f.y;
    }

    float sc = 1.0f + __ldg(eps);
    float4 yg = Y[g * 16 + c];             // residual stays fp32
    float4 bb = __ldg(b4 + c);
    a.x += sc * yg.x + bb.x;
    a.y += sc * yg.y + bb.y;
    a.z += sc * yg.z + bb.z;
    a.w += sc * yg.w + bb.w;
    out[g * 16 + c] = a;
}

// ---------------------------------------------------------------------------
// Launch: inputs per metadata order: feat, W, b, eps, src, dst
// Fork: CSR build (side stream) overlaps GEMM (main stream). 6 launches.
// ---------------------------------------------------------------------------
extern "C" void kernel_launch(void* const* d_in, const int* in_sizes, int n_in,
                              void* d_out, int out_size)
{
    const float4* feat = (const float4*)d_in[0];
    const float4* W    = (const float4*)d_in[1];
    const float4* b4   = (const float4*)d_in[2];
    const float*  eps  = (const float*)d_in[3];
    const int4*   src4 = (const int4*)d_in[4];
    const int4*   dst4 = (const int4*)d_in[5];
    float4*       out  = (float4*)d_out;

    int *cnt, *offs, *cursor, *sorted;
    float* Y;
    __half* Yh;
    cudaGetSymbolAddress((void**)&cnt,    g_cnt);
    cudaGetSymbolAddress((void**)&offs,   g_offs);
    cudaGetSymbolAddress((void**)&cursor, g_cursor);
    cudaGetSymbolAddress((void**)&sorted, g_sorted);
    cudaGetSymbolAddress((void**)&Y,      g_Y);
    cudaGetSymbolAddress((void**)&Yh,     g_Yh);

    const int EQ = (N_EDGES / 4 + 255) / 256;   // 782 blocks, 4 edges/thread

    // Fork: CSR build chain on side stream
    cudaEventRecord(g_evFork, 0);
    cudaStreamWaitEvent(g_side, g_evFork, 0);
    hist_kernel<<<EQ, 256, 0, g_side>>>(dst4, cnt);
    scanfin_kernel<<<NBLK, 256, 0, g_side>>>(cnt, offs, cursor);
    scatter_idx_kernel<<<EQ, 256, 0, g_side>>>(src4, dst4, cursor, sorted, cnt);
    cudaEventRecord(g_evJoin, g_side);

    // Main stream: Y = feat @ W^T (+ fp16 copy), overlaps the CSR build
    {
        int blocks = (N_NODES + GROWS - 1) / GROWS;
        gemm_y_kernel<<<blocks, GROWS>>>(feat, W, (float4*)Y, (uint2*)Yh);
    }

    // Join, then final gather writes out directly
    cudaStreamWaitEvent(0, g_evJoin, 0);
    {
        int threads = N_NODES * 16;
        gather_final_kernel<<<(threads + 255) / 256, 256>>>(
            (const float4*)Y, (const uint2*)Yh, offs, sorted, eps, b4, out);
    }
}